// round 9
// baseline (speedup 1.0000x reference)
#include <cuda_runtime.h>
#include <cuda_fp16.h>
#include <cstdint>

#define NU 100000
#define NM 50000
#define EDGES 1000000
#define HID 128
#define DIM 64

typedef unsigned long long ull;

// Precomputed per-node projections (fp16). __device__ globals = allowed scratch.
__device__ __half g_U[(size_t)NU * HID];
__device__ __half g_I[(size_t)NM * HID];
__device__ int g_idx32;   // 1 if index arrays are int32, 0 if int64

__device__ __forceinline__ ull pack_f32x2(float lo, float hi) {
    ull p;
    asm("mov.b64 %0, {%1, %2};" : "=l"(p)
        : "r"(__float_as_uint(lo)), "r"(__float_as_uint(hi)));
    return p;
}
__device__ __forceinline__ ull fma_f32x2(ull a, ull b, ull c) {
    ull r;
    asm("fma.rn.f32x2 %0, %1, %2, %3;" : "=l"(r) : "l"(a), "l"(b), "l"(c));
    return r;
}
__device__ __forceinline__ float2 unpack_f32x2(ull p) {
    unsigned int lo, hi;
    asm("mov.b64 {%0, %1}, %2;" : "=r"(lo), "=r"(hi) : "l"(p));
    return make_float2(__uint_as_float(lo), __uint_as_float(hi));
}

// ---------------------------------------------------------------------------
// Detect index dtype: int32 data read as int64 has nonzero hi words.
// ---------------------------------------------------------------------------
__global__ void detect_idx_kernel(const long long* __restrict__ src,
                                  const long long* __restrict__ dst) {
    long long v = src[threadIdx.x];
    long long w = dst[threadIdx.x];
    int any = (((unsigned long long)v >> 32) != 0ull) |
              (((unsigned long long)w >> 32) != 0ull);
    any = __syncthreads_or(any);
    if (threadIdx.x == 0) g_idx32 = any;
}

// ---------------------------------------------------------------------------
// Precompute: C[r][j] = sum_k A[r][k] * W1[j][kOff+k]  (+ b1[j] if given)
// R9: inner product in packed fma.rn.f32x2 (halves FFMA instr count; kernel
// is FMA-throughput bound per R8 profile). The broadcast multiplier is stored
// duplicated in smem (float2{a,a}) so it loads pre-packed via LDS.64.
// Wt drops its pad (smem = 32K + 16K = 48KB exact) and instead XOR-swizzles
// the 4-column group index by (k&31): the k-lane-fast coalesced fill is <=
// 4-way conflicted; the float4 compute reads stay conflict-free.
// ---------------------------------------------------------------------------
__global__ __launch_bounds__(256) void precompute_kernel(
    const float* __restrict__ A, int R,
    const float* __restrict__ W1, int kOff,
    const float* __restrict__ b1,     // may be null
    __half* __restrict__ C)
{
    __shared__ float  Wt[DIM][HID];   // Wt[k][swz(jg)*4+jl] = W1[j][kOff+k] (32KB)
    __shared__ float2 As2[32][DIM];   // duplicated (a,a)                    (16KB)

    const int tid = threadIdx.x;
    const int r0  = blockIdx.x * 32;

    // Fill Wt: lane-fast k (gmem-coalesced); column-group XOR swizzle.
    #pragma unroll
    for (int idx = tid; idx < DIM * HID; idx += 256) {
        int k = idx & 63;         // contiguous per lane
        int j = idx >> 6;
        int jg = j >> 2, jl = j & 3;
        Wt[k][((jg ^ (k & 31)) << 2) + jl] = W1[j * 128 + kOff + k];
    }
    for (int idx = tid; idx < 32 * DIM; idx += 256) {
        int r = idx >> 6, c = idx & 63;
        int gr = r0 + r;
        float v = (gr < R) ? A[(size_t)gr * DIM + c] : 0.f;
        As2[r][c] = make_float2(v, v);
    }
    __syncthreads();

    const int tx = tid & 31;   // output column group: cols tx*4 .. tx*4+3
    const int ty = tid >> 5;   // rows ty, ty+8, ty+16, ty+24

    ull acc2[4][2];            // [row][colpair]: (c0,c1),(c2,c3) as f32x2
    #pragma unroll
    for (int r = 0; r < 4; r++) { acc2[r][0] = 0ull; acc2[r][1] = 0ull; }

    #pragma unroll 8
    for (int k = 0; k < DIM; k++) {
        const ulonglong2 wp =
            *(const ulonglong2*)&Wt[k][(tx ^ (k & 31)) << 2];  // 16B-aligned
        #pragma unroll
        for (int r = 0; r < 4; r++) {
            ull ap = *(const ull*)&As2[ty + r * 8][k];   // broadcast LDS.64
            acc2[r][0] = fma_f32x2(ap, wp.x, acc2[r][0]);
            acc2[r][1] = fma_f32x2(ap, wp.y, acc2[r][1]);
        }
    }

    float4 bb = make_float4(0.f, 0.f, 0.f, 0.f);
    if (b1) bb = *(const float4*)&b1[tx * 4];

    #pragma unroll
    for (int r = 0; r < 4; r++) {
        int gr = r0 + ty + r * 8;
        if (gr < R) {
            float2 p0 = unpack_f32x2(acc2[r][0]);
            float2 p1 = unpack_f32x2(acc2[r][1]);
            __half2 h0 = __floats2half2_rn(p0.x + bb.x, p0.y + bb.y);
            __half2 h1 = __floats2half2_rn(p1.x + bb.z, p1.y + bb.w);
            __half2* cp = (__half2*)(C + (size_t)gr * HID + tx * 4);
            cp[0] = h0;
            cp[1] = h1;
        }
    }
}

// ---------------------------------------------------------------------------
// Edge pass: out[e][c] = sum_j relu(U[src[e]][j] + I[dst[e]][j]) * W2[c][j] + b2[c]
// 2 edges/warp (16 lanes each), 8 j's/lane, half2 relu + f32x2 dot (R8).
// R9: loop unrolled x2 with all 4 gathers batched before compute -> MLP
// per warp 2->4 (R8 profile: latency-bound, DRAM 5% / issue 49%).
// launch_bounds(256,3): cap 84 regs, 3 blocks/SM.
// ---------------------------------------------------------------------------
__device__ __forceinline__ void edge_compute_store(
    long long e, uint4 uv, uint4 iv, int g,
    const ull* __restrict__ w2q, float b2sel, float* __restrict__ out)
{
    const __half2* u2 = (const __half2*)&uv;
    const __half2* i2 = (const __half2*)&iv;
    const __half2 z = __float2half2_rn(0.f);

    ull h2[4];
    #pragma unroll
    for (int t = 0; t < 4; t++) {
        __half2 hv = __hmax2(__hadd2(u2[t], i2[t]), z);
        float2 f = __half22float2(hv);
        h2[t] = pack_f32x2(f.x, f.y);
    }

    float accs[5];
    #pragma unroll
    for (int c = 0; c < 5; c++) {
        ull a = 0ull;
        #pragma unroll
        for (int t = 0; t < 4; t++)
            a = fma_f32x2(h2[t], w2q[c * 4 + t], a);
        float2 p = unpack_f32x2(a);
        accs[c] = p.x + p.y;
    }

    #pragma unroll
    for (int off = 8; off >= 1; off >>= 1) {
        #pragma unroll
        for (int c = 0; c < 5; c++)
            accs[c] += __shfl_xor_sync(0xffffffffu, accs[c], off);
    }

    if (g < 5) {
        float v = accs[0];
        if (g == 1) v = accs[1];
        else if (g == 2) v = accs[2];
        else if (g == 3) v = accs[3];
        else if (g == 4) v = accs[4];
        out[e * 5 + g] = v + b2sel;
    }
}

template <typename IT>
__device__ __forceinline__ void edge_loop(
    const IT* __restrict__ src, const IT* __restrict__ dst,
    const __half* __restrict__ U, const __half* __restrict__ I,
    const ull* __restrict__ w2q, float b2sel, float* __restrict__ out,
    int warpId, int nWarps, int g, int sub)
{
    const int nPairs = EDGES / 2;
    int p = warpId;
    for (; p + nWarps < nPairs; p += 2 * nWarps) {
        const long long eA = 2LL * p + sub;
        const long long eB = 2LL * (p + nWarps) + sub;
        int sA = (int)src[eA], dA = (int)dst[eA];
        int sB = (int)src[eB], dB = (int)dst[eB];
        // batch all 4 gathers before any compute (MLP=4)
        uint4 uvA = *(const uint4*)(U + (size_t)sA * HID + g * 8);
        uint4 ivA = *(const uint4*)(I + (size_t)dA * HID + g * 8);
        uint4 uvB = *(const uint4*)(U + (size_t)sB * HID + g * 8);
        uint4 ivB = *(const uint4*)(I + (size_t)dB * HID + g * 8);
        edge_compute_store(eA, uvA, ivA, g, w2q, b2sel, out);
        edge_compute_store(eB, uvB, ivB, g, w2q, b2sel, out);
    }
    if (p < nPairs) {
        const long long e = 2LL * p + sub;
        int s = (int)src[e], d = (int)dst[e];
        uint4 uv = *(const uint4*)(U + (size_t)s * HID + g * 8);
        uint4 iv = *(const uint4*)(I + (size_t)d * HID + g * 8);
        edge_compute_store(e, uv, iv, g, w2q, b2sel, out);
    }
}

__global__ __launch_bounds__(256, 3) void edge_kernel(
    const void* __restrict__ src_raw, const void* __restrict__ dst_raw,
    const __half* __restrict__ U, const __half* __restrict__ I,
    const float* __restrict__ W2, const float* __restrict__ b2,
    float* __restrict__ out)
{
    const int lane = threadIdx.x & 31;
    const int g    = lane & 15;      // j-group within my edge
    const int sub  = lane >> 4;      // which edge of the warp's pair
    const int warpId = (blockIdx.x * blockDim.x + threadIdx.x) >> 5;
    const int nWarps = (gridDim.x * blockDim.x) >> 5;

    // Preload W2 slice as 20 packed f32x2: W2[c][g*8 .. g*8+7]
    ull w2q[20];
    #pragma unroll
    for (int c = 0; c < 5; c++) {
        float4 a = *(const float4*)(W2 + c * HID + g * 8);
        float4 b = *(const float4*)(W2 + c * HID + g * 8 + 4);
        w2q[c * 4 + 0] = pack_f32x2(a.x, a.y);
        w2q[c * 4 + 1] = pack_f32x2(a.z, a.w);
        w2q[c * 4 + 2] = pack_f32x2(b.x, b.y);
        w2q[c * 4 + 3] = pack_f32x2(b.z, b.w);
    }
    const float b2sel = b2[g < 5 ? g : 0];

    if (g_idx32) {
        edge_loop((const int*)src_raw, (const int*)dst_raw,
                  U, I, w2q, b2sel, out, warpId, nWarps, g, sub);
    } else {
        edge_loop((const long long*)src_raw, (const long long*)dst_raw,
                  U, I, w2q, b2sel, out, warpId, nWarps, g, sub);
    }
}

// ---------------------------------------------------------------------------
// Launch. Inputs: ufeat, ifeat, W1, b1, W2, b2, src_idx, dst_idx. Out: [E,5] f32.
// ---------------------------------------------------------------------------
extern "C" void kernel_launch(void* const* d_in, const int* in_sizes, int n_in,
                              void* d_out, int out_size) {
    (void)in_sizes; (void)n_in; (void)out_size;
    const float* ufeat = (const float*)d_in[0];
    const float* ifeat = (const float*)d_in[1];
    const float* W1    = (const float*)d_in[2];
    const float* b1    = (const float*)d_in[3];
    const float* W2    = (const float*)d_in[4];
    const float* b2    = (const float*)d_in[5];
    const void*  src   = d_in[6];
    const void*  dst   = d_in[7];
    float* out = (float*)d_out;

    __half *U, *I;
    cudaGetSymbolAddress((void**)&U, g_U);
    cudaGetSymbolAddress((void**)&I, g_I);

    detect_idx_kernel<<<1, 256>>>((const long long*)src, (const long long*)dst);
    precompute_kernel<<<(NU + 31) / 32, 256>>>(ufeat, NU, W1, 0,  b1,      U);
    precompute_kernel<<<(NM + 31) / 32, 256>>>(ifeat, NM, W1, 64, nullptr, I);
    edge_kernel<<<2368, 256>>>(src, dst, U, I, W2, b2, out);
}

// round 11
// speedup vs baseline: 1.1581x; 1.1581x over previous
#include <cuda_runtime.h>
#include <cuda_fp16.h>
#include <cstdint>

#define NU 100000
#define NM 50000
#define EDGES 1000000
#define HID 128
#define DIM 64

typedef unsigned long long ull;

// Precomputed per-node projections (fp16). __device__ globals = allowed scratch.
__device__ __half g_U[(size_t)NU * HID];
__device__ __half g_I[(size_t)NM * HID];
__device__ int g_idx32;   // 1 if index arrays are int32, 0 if int64

// ---------------------------------------------------------------------------
// Detect index dtype: int32 data read as int64 has nonzero hi words.
// ---------------------------------------------------------------------------
__global__ void detect_idx_kernel(const long long* __restrict__ src,
                                  const long long* __restrict__ dst) {
    long long v = src[threadIdx.x];
    long long w = dst[threadIdx.x];
    int any = (((unsigned long long)v >> 32) != 0ull) |
              (((unsigned long long)w >> 32) != 0ull);
    any = __syncthreads_or(any);
    if (threadIdx.x == 0) g_idx32 = any;
}

// ---------------------------------------------------------------------------
// Precompute (R8 version, measured ~94us, near FFMA floor):
// C[r][j] = sum_k A[r][k] * W1[j][kOff + k]  (+ b1[j] if given)
// Coalesced lane-fast-k Wt fill, HIDP=132 pad, 4x4 register tile / thread.
// ---------------------------------------------------------------------------
#define HIDP 132   // HID + 4 pad: keeps 16B alignment, breaks STS conflicts

__global__ __launch_bounds__(256) void precompute_kernel(
    const float* __restrict__ A, int R,
    const float* __restrict__ W1, int kOff,
    const float* __restrict__ b1,     // may be null
    __half* __restrict__ C)
{
    __shared__ float Wt[DIM][HIDP];   // Wt[k][j] = W1[j][kOff+k]  (~33.8 KB)
    __shared__ float As[32][DIM];     // A tile                     (8 KB)

    const int tid = threadIdx.x;
    const int r0  = blockIdx.x * 32;

    #pragma unroll
    for (int idx = tid; idx < DIM * HID; idx += 256) {
        int k = idx & 63;         // contiguous per lane (gmem-coalesced)
        int j = idx >> 6;
        Wt[k][j] = W1[j * 128 + kOff + k];
    }
    for (int idx = tid; idx < 32 * DIM; idx += 256) {
        int r = idx >> 6, c = idx & 63;
        int gr = r0 + r;
        As[r][c] = (gr < R) ? A[(size_t)gr * DIM + c] : 0.f;
    }
    __syncthreads();

    const int tx = tid & 31;   // output column group: cols tx*4 .. tx*4+3
    const int ty = tid >> 5;   // rows ty, ty+8, ty+16, ty+24

    float acc[4][4];
    #pragma unroll
    for (int r = 0; r < 4; r++)
        #pragma unroll
        for (int c = 0; c < 4; c++) acc[r][c] = 0.f;

    #pragma unroll 8
    for (int k = 0; k < DIM; k++) {
        float4 w = *(const float4*)&Wt[k][tx * 4];
        #pragma unroll
        for (int r = 0; r < 4; r++) {
            float a = As[ty + r * 8][k];   // warp-broadcast LDS
            acc[r][0] = fmaf(a, w.x, acc[r][0]);
            acc[r][1] = fmaf(a, w.y, acc[r][1]);
            acc[r][2] = fmaf(a, w.z, acc[r][2]);
            acc[r][3] = fmaf(a, w.w, acc[r][3]);
        }
    }

    float4 bb = make_float4(0.f, 0.f, 0.f, 0.f);
    if (b1) bb = *(const float4*)&b1[tx * 4];

    #pragma unroll
    for (int r = 0; r < 4; r++) {
        int gr = r0 + ty + r * 8;
        if (gr < R) {
            __half2 h0 = __floats2half2_rn(acc[r][0] + bb.x, acc[r][1] + bb.y);
            __half2 h1 = __floats2half2_rn(acc[r][2] + bb.z, acc[r][3] + bb.w);
            __half2* cp = (__half2*)(C + (size_t)gr * HID + tx * 4);
            cp[0] = h0;
            cp[1] = h1;
        }
    }
}

// ---------------------------------------------------------------------------
// Edge pass: out[e][c] = sum_j relu(U[src[e]][j] + I[dst[e]][j]) * W2[c][j] + b2[c]
// 2 edges/warp (16 lanes each), 8 j's/lane, MLP4 unroll (R9).
// R11: W2 slice held as fp16 half2 (20 regs, was 40 fp32-packed); dot done
// with HFMA2 directly on the relu'd half2 values (kills the f32x2 packing
// stage), per-lane fp16 partials span only 4 products, converted to fp32
// before the 16-lane shuffle reduce. launch_bounds(256,5) -> 51-reg cap,
// target 40 warps/SM (62.5% occ vs R9's 35%).
// ---------------------------------------------------------------------------
__device__ __forceinline__ void edge_compute_store(
    long long e, uint4 uv, uint4 iv, int g,
    const uint32_t* __restrict__ w2h,   // 20 x half2 regs: [c][t]
    float b2sel, float* __restrict__ out)
{
    const __half2* u2 = (const __half2*)&uv;
    const __half2* i2 = (const __half2*)&iv;
    const __half2 z = __float2half2_rn(0.f);

    __half2 h2[4];
    #pragma unroll
    for (int t = 0; t < 4; t++)
        h2[t] = __hmax2(__hadd2(u2[t], i2[t]), z);   // relu, stays fp16

    float accs[5];
    #pragma unroll
    for (int c = 0; c < 5; c++) {
        __half2 ha = z;
        #pragma unroll
        for (int t = 0; t < 4; t++) {
            __half2 w = *reinterpret_cast<const __half2*>(&w2h[c * 4 + t]);
            ha = __hfma2(h2[t], w, ha);              // fp16 partial (4 products)
        }
        float2 f = __half22float2(ha);               // to fp32 before reduce
        accs[c] = f.x + f.y;
    }

    // reduce across the 16 lanes of this edge-group (both groups in parallel)
    #pragma unroll
    for (int off = 8; off >= 1; off >>= 1) {
        #pragma unroll
        for (int c = 0; c < 5; c++)
            accs[c] += __shfl_xor_sync(0xffffffffu, accs[c], off);
    }

    if (g < 5) {
        float v = accs[0];
        if (g == 1) v = accs[1];
        else if (g == 2) v = accs[2];
        else if (g == 3) v = accs[3];
        else if (g == 4) v = accs[4];
        out[e * 5 + g] = v + b2sel;
    }
}

template <typename IT>
__device__ __forceinline__ void edge_loop(
    const IT* __restrict__ src, const IT* __restrict__ dst,
    const __half* __restrict__ U, const __half* __restrict__ I,
    const uint32_t* __restrict__ w2h, float b2sel, float* __restrict__ out,
    int warpId, int nWarps, int g, int sub)
{
    const int nPairs = EDGES / 2;
    int p = warpId;
    for (; p + nWarps < nPairs; p += 2 * nWarps) {
        const long long eA = 2LL * p + sub;
        const long long eB = 2LL * (p + nWarps) + sub;
        int sA = (int)src[eA], dA = (int)dst[eA];
        int sB = (int)src[eB], dB = (int)dst[eB];
        // batch all 4 gathers before any compute (MLP=4)
        uint4 uvA = *(const uint4*)(U + (size_t)sA * HID + g * 8);
        uint4 ivA = *(const uint4*)(I + (size_t)dA * HID + g * 8);
        uint4 uvB = *(const uint4*)(U + (size_t)sB * HID + g * 8);
        uint4 ivB = *(const uint4*)(I + (size_t)dB * HID + g * 8);
        edge_compute_store(eA, uvA, ivA, g, w2h, b2sel, out);
        edge_compute_store(eB, uvB, ivB, g, w2h, b2sel, out);
    }
    if (p < nPairs) {
        const long long e = 2LL * p + sub;
        int s = (int)src[e], d = (int)dst[e];
        uint4 uv = *(const uint4*)(U + (size_t)s * HID + g * 8);
        uint4 iv = *(const uint4*)(I + (size_t)d * HID + g * 8);
        edge_compute_store(e, uv, iv, g, w2h, b2sel, out);
    }
}

__global__ __launch_bounds__(256, 5) void edge_kernel(
    const void* __restrict__ src_raw, const void* __restrict__ dst_raw,
    const __half* __restrict__ U, const __half* __restrict__ I,
    const float* __restrict__ W2, const float* __restrict__ b2,
    float* __restrict__ out)
{
    const int lane = threadIdx.x & 31;
    const int g    = lane & 15;
    const int sub  = lane >> 4;
    const int warpId = (blockIdx.x * blockDim.x + threadIdx.x) >> 5;
    const int nWarps = (gridDim.x * blockDim.x) >> 5;

    // Preload W2 slice as fp16: w2h[c][t] = half2(W2[c][g*8+2t], W2[c][g*8+2t+1])
    uint32_t w2h[20];
    #pragma unroll
    for (int c = 0; c < 5; c++) {
        float4 a = *(const float4*)(W2 + c * HID + g * 8);
        float4 b = *(const float4*)(W2 + c * HID + g * 8 + 4);
        __half2 p0 = __floats2half2_rn(a.x, a.y);
        __half2 p1 = __floats2half2_rn(a.z, a.w);
        __half2 p2 = __floats2half2_rn(b.x, b.y);
        __half2 p3 = __floats2half2_rn(b.z, b.w);
        w2h[c * 4 + 0] = *reinterpret_cast<uint32_t*>(&p0);
        w2h[c * 4 + 1] = *reinterpret_cast<uint32_t*>(&p1);
        w2h[c * 4 + 2] = *reinterpret_cast<uint32_t*>(&p2);
        w2h[c * 4 + 3] = *reinterpret_cast<uint32_t*>(&p3);
    }
    const float b2sel = b2[g < 5 ? g : 0];

    if (g_idx32) {
        edge_loop((const int*)src_raw, (const int*)dst_raw,
                  U, I, w2h, b2sel, out, warpId, nWarps, g, sub);
    } else {
        edge_loop((const long long*)src_raw, (const long long*)dst_raw,
                  U, I, w2h, b2sel, out, warpId, nWarps, g, sub);
    }
}

// ---------------------------------------------------------------------------
// Launch. Inputs: ufeat, ifeat, W1, b1, W2, b2, src_idx, dst_idx. Out: [E,5] f32.
// ---------------------------------------------------------------------------
extern "C" void kernel_launch(void* const* d_in, const int* in_sizes, int n_in,
                              void* d_out, int out_size) {
    (void)in_sizes; (void)n_in; (void)out_size;
    const float* ufeat = (const float*)d_in[0];
    const float* ifeat = (const float*)d_in[1];
    const float* W1    = (const float*)d_in[2];
    const float* b1    = (const float*)d_in[3];
    const float* W2    = (const float*)d_in[4];
    const float* b2    = (const float*)d_in[5];
    const void*  src   = d_in[6];
    const void*  dst   = d_in[7];
    float* out = (float*)d_out;

    __half *U, *I;
    cudaGetSymbolAddress((void**)&U, g_U);
    cudaGetSymbolAddress((void**)&I, g_I);

    detect_idx_kernel<<<1, 256>>>((const long long*)src, (const long long*)dst);
    precompute_kernel<<<(NU + 31) / 32, 256>>>(ufeat, NU, W1, 0,  b1,      U);
    precompute_kernel<<<(NM + 31) / 32, 256>>>(ifeat, NM, W1, 64, nullptr, I);
    edge_kernel<<<2368, 256>>>(src, dst, U, I, W2, b2, out);
}